// round 1
// baseline (speedup 1.0000x reference)
#include <cuda_runtime.h>

#define Bq 2
#define Tq 4096
#define Dq 1024
#define Cq 512
#define Pq 16
#define Hq 2048
#define FFNq 4096
#define Sq (Pq + 2*Cq)          // 1040
#define MC (Bq*Cq)              // 1024
#define MS (Bq*Sq)              // 2080
#define NCHUNK (Tq/Cq)          // 8

#define ACT_NONE 0
#define ACT_SILU 1
#define ACT_SIG  2

// ---------------- scratch layout (one big device buffer) ----------------
typedef long long ll;
static const ll L_MCD = (ll)MC*Dq;
static const ll L_MCH = (ll)MC*Hq;
static const ll L_MSD = (ll)MS*Dq;
static const ll L_SC  = (ll)MC*Sq;
static const ll L_W0  = (ll)Dq*Hq;
static const ll L_FF  = (ll)MC*FFNq;

#define O_SEG  0LL
#define O_QN   (O_SEG  + (ll)MC*Dq)
#define O_PRE  (O_QN   + (ll)MC*Dq)
#define O_HSIL (O_PRE  + (ll)MC*Hq)
#define O_H    (O_HSIL + (ll)MC*Hq)
#define O_AUG  (O_H    + (ll)MC*Dq)
#define O_LN   (O_AUG  + (ll)MS*Dq)
#define O_Q    (O_LN   + (ll)MS*Dq)
#define O_K    (O_Q    + (ll)MC*Dq)
#define O_V    (O_K    + (ll)MS*Dq)
#define O_SCR  (O_V    + (ll)MS*Dq)
#define O_ATT  (O_SCR  + (ll)MC*Sq)
#define O_YT   (O_ATT  + (ll)MC*Dq)
#define O_KK   (O_YT   + (ll)MC*Dq)
#define O_VV   (O_KK   + (ll)MC*Dq)
#define O_YM   (O_VV   + (ll)MC*Dq)
#define O_E    (O_YM   + (ll)MC*Dq)
#define O_DH   (O_E    + (ll)MC*Dq)
#define O_GW0  (O_DH   + (ll)MC*Hq)
#define O_GW1  (O_GW0  + (ll)Dq*Hq)
#define O_GB0  (O_GW1  + (ll)Hq*Dq)
#define O_GB1  (O_GB0  + Hq)
#define O_W0   (O_GB1  + Dq)
#define O_B0   (O_W0   + (ll)Dq*Hq)
#define O_W1   (O_B0   + Hq)
#define O_B1   (O_W1   + (ll)Hq*Dq)
#define O_M0   (O_B1   + Dq)
#define O_MB0  (O_M0   + (ll)Dq*Hq)
#define O_M1   (O_MB0  + Hq)
#define O_MB1  (O_M1   + (ll)Hq*Dq)
#define O_MO   (O_MB1  + Dq)
#define O_LNY  (O_MO   + (ll)MC*Dq)
#define O_GATE (O_LNY  + (ll)MC*Dq)
#define O_O    (O_GATE + (ll)MC*Dq)
#define O_FFH  (O_O    + (ll)MC*Dq)
#define O_END  (O_FFH  + (ll)MC*FFNq)

__device__ float g_buf[O_END];

// ---------------- generic tiled SGEMM ----------------
// C(M,N) = act( opA(A) @ opB(B) + bias ) + residual
// TA: A element (m,k) at A[k*lda+m] ; TB: B element (k,n) at B[n*ldb+k]
#define BM 64
#define BN 64
#define BK 16

template<int TA, int TB>
__global__ __launch_bounds__(256)
void gemm_k(const float* __restrict__ A, const float* __restrict__ Bm,
            const float* __restrict__ bias, const float* __restrict__ R,
            float* __restrict__ Cc,
            int M, int N, int K, int lda, int ldb, int ldc, int ldr,
            ll sA, ll sB, ll sR, ll sC, int act)
{
    __shared__ float As[BK][BM+4];
    __shared__ float Bs[BK][BN+4];
    int bz = blockIdx.z;
    A  += (ll)bz * sA;
    Bm += (ll)bz * sB;
    Cc += (ll)bz * sC;
    const float* Rp = R ? (R + (ll)bz * sR) : (const float*)0;

    int row0 = blockIdx.y * BM;
    int col0 = blockIdx.x * BN;
    int tid = threadIdx.x;
    int tx = tid & 15, ty = tid >> 4;

    float acc[4][4];
#pragma unroll
    for (int i = 0; i < 4; i++)
#pragma unroll
        for (int j = 0; j < 4; j++) acc[i][j] = 0.f;

    for (int k0 = 0; k0 < K; k0 += BK) {
        // ---- load A tile ----
        if (TA == 0) {
            int m  = tid >> 2;
            int kk = (tid & 3) * 4;
            int gm = row0 + m;
            float4 v = make_float4(0.f,0.f,0.f,0.f);
            if (gm < M) v = *(const float4*)(A + (ll)gm * lda + k0 + kk);
            As[kk+0][m] = v.x; As[kk+1][m] = v.y; As[kk+2][m] = v.z; As[kk+3][m] = v.w;
        } else {
            int kk = tid >> 4;
            int m4 = (tid & 15) * 4;
            int gm = row0 + m4;
            float4 v = make_float4(0.f,0.f,0.f,0.f);
            if (gm < M) v = *(const float4*)(A + (ll)(k0+kk) * lda + gm);
            As[kk][m4+0] = v.x; As[kk][m4+1] = v.y; As[kk][m4+2] = v.z; As[kk][m4+3] = v.w;
        }
        // ---- load B tile ----
        if (TB == 0) {
            int kk = tid >> 4;
            int n4 = (tid & 15) * 4;
            int gn = col0 + n4;
            float4 v = make_float4(0.f,0.f,0.f,0.f);
            if (gn < N) v = *(const float4*)(Bm + (ll)(k0+kk) * ldb + gn);
            Bs[kk][n4+0] = v.x; Bs[kk][n4+1] = v.y; Bs[kk][n4+2] = v.z; Bs[kk][n4+3] = v.w;
        } else {
            int n  = tid >> 2;
            int kk = (tid & 3) * 4;
            int gn = col0 + n;
            float4 v = make_float4(0.f,0.f,0.f,0.f);
            if (gn < N) v = *(const float4*)(Bm + (ll)gn * ldb + k0 + kk);
            Bs[kk+0][n] = v.x; Bs[kk+1][n] = v.y; Bs[kk+2][n] = v.z; Bs[kk+3][n] = v.w;
        }
        __syncthreads();
#pragma unroll
        for (int kk = 0; kk < BK; kk++) {
            float a0 = As[kk][ty], a1 = As[kk][ty+16], a2 = As[kk][ty+32], a3 = As[kk][ty+48];
            float b0 = Bs[kk][tx], b1 = Bs[kk][tx+16], b2 = Bs[kk][tx+32], b3 = Bs[kk][tx+48];
            acc[0][0] += a0*b0; acc[0][1] += a0*b1; acc[0][2] += a0*b2; acc[0][3] += a0*b3;
            acc[1][0] += a1*b0; acc[1][1] += a1*b1; acc[1][2] += a1*b2; acc[1][3] += a1*b3;
            acc[2][0] += a2*b0; acc[2][1] += a2*b1; acc[2][2] += a2*b2; acc[2][3] += a2*b3;
            acc[3][0] += a3*b0; acc[3][1] += a3*b1; acc[3][2] += a3*b2; acc[3][3] += a3*b3;
        }
        __syncthreads();
    }

#pragma unroll
    for (int i = 0; i < 4; i++) {
        int r = row0 + ty + 16*i;
        if (r >= M) continue;
#pragma unroll
        for (int j = 0; j < 4; j++) {
            int c = col0 + tx + 16*j;
            if (c >= N) continue;
            float v = acc[i][j];
            if (bias) v += bias[c];
            if (act == ACT_SILU) { float s = 1.f/(1.f + __expf(-v)); v = v*s; }
            else if (act == ACT_SIG) { v = 1.f/(1.f + __expf(-v)); }
            if (Rp) v += Rp[(ll)r * ldr + c];
            Cc[(ll)r * ldc + c] = v;
        }
    }
}

// ---------------- elementwise / reduction kernels ----------------
__global__ void seg_k(float* __restrict__ seg, const float* __restrict__ x, int ch)
{
    ll i = (ll)blockIdx.x * blockDim.x + threadIdx.x;
    if (i >= L_MCD) return;
    int d = (int)(i % Dq);
    ll row = i / Dq;
    int b = (int)(row / Cq), t = (int)(row % Cq);
    seg[i] = x[((ll)b*Tq + (ll)ch*Cq + t) * Dq + d];
}

__global__ void aug_k(float* __restrict__ aug, const float* __restrict__ pers,
                      const float* __restrict__ h, const float* __restrict__ seg)
{
    ll i = (ll)blockIdx.x * blockDim.x + threadIdx.x;
    if (i >= L_MSD) return;
    int d = (int)(i % Dq);
    ll row = i / Dq;
    int b = (int)(row / Sq), s = (int)(row % Sq);
    float v;
    if (s < Pq)            v = pers[(ll)s*Dq + d];
    else if (s < Pq+Cq)    v = h[((ll)b*Cq + (s-Pq)) * Dq + d];
    else                   v = seg[((ll)b*Cq + (s-Pq-Cq)) * Dq + d];
    aug[i] = v;
}

__global__ void l2norm_k(float* __restrict__ x, float scale)
{
    ll row = blockIdx.x;
    float* p = x + row * Dq;
    __shared__ float red[256];
    int t = threadIdx.x;
    float s = 0.f;
    for (int j = t; j < Dq; j += 256) { float v = p[j]; s += v*v; }
    red[t] = s; __syncthreads();
    for (int k = 128; k > 0; k >>= 1) { if (t < k) red[t] += red[t+k]; __syncthreads(); }
    float inv = scale / fmaxf(sqrtf(red[0]), 1e-12f);
    for (int j = t; j < Dq; j += 256) p[j] *= inv;
}

__global__ void ln_k(const float* __restrict__ src, float* __restrict__ dst,
                     const float* __restrict__ g, const float* __restrict__ b)
{
    ll row = blockIdx.x;
    const float* p = src + row * Dq;
    float* q = dst + row * Dq;
    __shared__ float red[256];
    int t = threadIdx.x;
    float s = 0.f;
    for (int j = t; j < Dq; j += 256) s += p[j];
    red[t] = s; __syncthreads();
    for (int k = 128; k > 0; k >>= 1) { if (t < k) red[t] += red[t+k]; __syncthreads(); }
    float mean = red[0] / (float)Dq;
    __syncthreads();
    float vs = 0.f;
    for (int j = t; j < Dq; j += 256) { float d = p[j] - mean; vs += d*d; }
    red[t] = vs; __syncthreads();
    for (int k = 128; k > 0; k >>= 1) { if (t < k) red[t] += red[t+k]; __syncthreads(); }
    float inv = rsqrtf(red[0] / (float)Dq + 1e-5f);
    for (int j = t; j < Dq; j += 256) q[j] = (p[j] - mean) * inv * g[j] + b[j];
}

__global__ void softmax_k(float* __restrict__ sc)
{
    ll row = blockIdx.x;               // 0..MC-1 (b*Cq + qi)
    int qi = (int)(row % Cq);
    float* p = sc + row * Sq;
    int L = Pq + Cq + qi + 1;
    __shared__ float red[256];
    int t = threadIdx.x;
    float mx = -1e30f;
    for (int j = t; j < L; j += 256) mx = fmaxf(mx, p[j]);
    red[t] = mx; __syncthreads();
    for (int k = 128; k > 0; k >>= 1) { if (t < k) red[t] = fmaxf(red[t], red[t+k]); __syncthreads(); }
    mx = red[0]; __syncthreads();
    float sum = 0.f;
    for (int j = t; j < L; j += 256) { float e = __expf(p[j] - mx); p[j] = e; sum += e; }
    red[t] = sum; __syncthreads();
    for (int k = 128; k > 0; k >>= 1) { if (t < k) red[t] += red[t+k]; __syncthreads(); }
    float inv = 1.f / red[0];
    for (int j = t; j < L; j += 256) p[j] *= inv;
    for (int j = L + t; j < Sq; j += 256) p[j] = 0.f;
}

__global__ void silu_k(float* __restrict__ dst, const float* __restrict__ src, ll n)
{
    ll i = (ll)blockIdx.x * blockDim.x + threadIdx.x;
    if (i >= n) return;
    float z = src[i];
    float s = 1.f / (1.f + __expf(-z));
    dst[i] = z * s;
}

__global__ void e_k(float* __restrict__ e, const float* __restrict__ ym,
                    const float* __restrict__ vv, ll n)
{
    ll i = (ll)blockIdx.x * blockDim.x + threadIdx.x;
    if (i >= n) return;
    e[i] = (ym[i] - vv[i]) * (1.f / (float)MC);
}

__global__ void dsilu_k(float* __restrict__ dh, const float* __restrict__ pre, ll n)
{
    ll i = (ll)blockIdx.x * blockDim.x + threadIdx.x;
    if (i >= n) return;
    float z = pre[i];
    float s = 1.f / (1.f + __expf(-z));
    dh[i] *= s * (1.f + z * (1.f - s));
}

__global__ void colsum_k(float* __restrict__ dst, const float* __restrict__ src, int Mr, int N)
{
    int c = blockIdx.x * blockDim.x + threadIdx.x;
    if (c >= N) return;
    float s = 0.f;
    for (int r = 0; r < Mr; r++) s += src[(ll)r * N + c];
    dst[c] = s;
}

__global__ void update_k(float* __restrict__ p, float* __restrict__ m,
                         const float* __restrict__ g, ll n)
{
    ll i = (ll)blockIdx.x * blockDim.x + threadIdx.x;
    if (i >= n) return;
    float mm = 0.9f * m[i] + g[i];
    m[i] = mm;
    p[i] = 0.99f * p[i] - 0.01f * mm;
}

__global__ void combine_k(float* __restrict__ o, const float* __restrict__ yt,
                          const float* __restrict__ gate, const float* __restrict__ mo, ll n)
{
    ll i = (ll)blockIdx.x * blockDim.x + threadIdx.x;
    if (i >= n) return;
    float g = gate[i];
    o[i] = yt[i] * g + mo[i] * (1.f - g);
}

// ---------------- host helpers ----------------
static inline int blks(ll n) { return (int)((n + 255) / 256); }

static void gemm(int TA, int TB,
                 const float* A, const float* B, const float* bias, const float* R, float* C,
                 int M, int N, int K, int lda, int ldb, int ldc, int ldr,
                 ll sA, ll sB, ll sR, ll sC, int batch, int act)
{
    dim3 grid((N + BN - 1) / BN, (M + BM - 1) / BM, batch);
    if (TA == 0 && TB == 0)
        gemm_k<0,0><<<grid, 256>>>(A,B,bias,R,C,M,N,K,lda,ldb,ldc,ldr,sA,sB,sR,sC,act);
    else if (TA == 1)
        gemm_k<1,0><<<grid, 256>>>(A,B,bias,R,C,M,N,K,lda,ldb,ldc,ldr,sA,sB,sR,sC,act);
    else
        gemm_k<0,1><<<grid, 256>>>(A,B,bias,R,C,M,N,K,lda,ldb,ldc,ldr,sA,sB,sR,sC,act);
}

extern "C" void kernel_launch(void* const* d_in, const int* in_sizes, int n_in,
                              void* d_out, int out_size)
{
    (void)in_sizes; (void)n_in; (void)out_size;
    const float* x         = (const float*)d_in[0];
    const float* wq_ctx    = (const float*)d_in[1];
    const float* wq        = (const float*)d_in[2];
    const float* wk        = (const float*)d_in[3];
    const float* wv        = (const float*)d_in[4];
    const float* w_attn_out= (const float*)d_in[5];
    const float* w_gate    = (const float*)d_in[6];
    const float* gate_g    = (const float*)d_in[7];
    const float* gate_b    = (const float*)d_in[8];
    const float* n1_g      = (const float*)d_in[9];
    const float* n1_b      = (const float*)d_in[10];
    const float* n2_g      = (const float*)d_in[11];
    const float* n2_b      = (const float*)d_in[12];
    const float* ffn_w1    = (const float*)d_in[13];
    const float* ffn_b1    = (const float*)d_in[14];
    const float* ffn_w2    = (const float*)d_in[15];
    const float* ffn_b2    = (const float*)d_in[16];
    const float* pers      = (const float*)d_in[17];
    const float* mem_w0    = (const float*)d_in[18];
    const float* mem_b0    = (const float*)d_in[19];
    const float* mem_w1    = (const float*)d_in[20];
    const float* mem_b1    = (const float*)d_in[21];
    const float* mem_wk    = (const float*)d_in[22];
    const float* mem_wv    = (const float*)d_in[23];
    float* out = (float*)d_out;

    float* base;
    cudaGetSymbolAddress((void**)&base, g_buf);

    float* seg  = base + O_SEG;
    float* qn   = base + O_QN;
    float* pre  = base + O_PRE;
    float* hsil = base + O_HSIL;
    float* hbuf = base + O_H;
    float* aug  = base + O_AUG;
    float* lnag = base + O_LN;
    float* qb   = base + O_Q;
    float* kb   = base + O_K;
    float* vb   = base + O_V;
    float* scr  = base + O_SCR;
    float* att  = base + O_ATT;
    float* yt   = base + O_YT;
    float* kk   = base + O_KK;
    float* vv   = base + O_VV;
    float* ym   = base + O_YM;
    float* eb   = base + O_E;
    float* dh   = base + O_DH;
    float* gw0  = base + O_GW0;
    float* gw1  = base + O_GW1;
    float* gb0  = base + O_GB0;
    float* gb1  = base + O_GB1;
    float* W0p  = base + O_W0;
    float* B0p  = base + O_B0;
    float* W1p  = base + O_W1;
    float* B1p  = base + O_B1;
    float* M0p  = base + O_M0;
    float* MB0p = base + O_MB0;
    float* M1p  = base + O_M1;
    float* MB1p = base + O_MB1;
    float* mo   = base + O_MO;
    float* lny  = base + O_LNY;
    float* gate = base + O_GATE;
    float* ob   = base + O_O;
    float* ffh  = base + O_FFH;

    // init memory state + zero momentum (every call: deterministic)
    cudaMemcpyAsync(W0p, mem_w0, L_W0 * sizeof(float), cudaMemcpyDeviceToDevice);
    cudaMemcpyAsync(B0p, mem_b0, Hq   * sizeof(float), cudaMemcpyDeviceToDevice);
    cudaMemcpyAsync(W1p, mem_w1, L_W0 * sizeof(float), cudaMemcpyDeviceToDevice);
    cudaMemcpyAsync(B1p, mem_b1, Dq   * sizeof(float), cudaMemcpyDeviceToDevice);
    cudaMemsetAsync(M0p,  0, L_W0 * sizeof(float));
    cudaMemsetAsync(MB0p, 0, Hq   * sizeof(float));
    cudaMemsetAsync(M1p,  0, L_W0 * sizeof(float));
    cudaMemsetAsync(MB1p, 0, Dq   * sizeof(float));

    for (int ch = 0; ch < NCHUNK; ch++) {
        // gather chunk
        seg_k<<<blks(L_MCD), 256>>>(seg, x, ch);

        // h = mem_mlp(mem, l2norm(seg @ wq_ctx))
        gemm(0,0, seg, wq_ctx, 0, 0, qn, MC, Dq, Dq, Dq, Dq, Dq, 0, 0,0,0,0, 1, ACT_NONE);
        l2norm_k<<<MC, 256>>>(qn, 1.0f);
        gemm(0,0, qn, W0p, B0p, 0, hsil, MC, Hq, Dq, Dq, Hq, Hq, 0, 0,0,0,0, 1, ACT_SILU);
        gemm(0,0, hsil, W1p, B1p, 0, hbuf, MC, Dq, Hq, Hq, Dq, Dq, 0, 0,0,0,0, 1, ACT_NONE);

        // aug + LN
        aug_k<<<blks(L_MSD), 256>>>(aug, pers, hbuf, seg);
        ln_k<<<MS, 256>>>(aug, lnag, n1_g, n1_b);

        // k, v over full S; q only for last C rows
        gemm(0,0, lnag, wk, 0, 0, kb, MS, Dq, Dq, Dq, Dq, Dq, 0, 0,0,0,0, 1, ACT_NONE);
        l2norm_k<<<MS, 256>>>(kb, 1.0f);
        gemm(0,0, lnag, wv, 0, 0, vb, MS, Dq, Dq, Dq, Dq, Dq, 0, 0,0,0,0, 1, ACT_NONE);
        gemm(0,0, lnag + (ll)(Pq+Cq)*Dq, wq, 0, 0, qb, Cq, Dq, Dq, Dq, Dq, Dq, 0,
             (ll)Sq*Dq, 0, 0, (ll)Cq*Dq, Bq, ACT_NONE);
        l2norm_k<<<MC, 256>>>(qb, 32.0f);   // * sqrt(D)

        // scores = q @ k^T (batched), causal softmax, @ v, @ w_attn_out + seg
        gemm(0,1, qb, kb, 0, 0, scr, Cq, Sq, Dq, Dq, Dq, Sq, 0,
             (ll)Cq*Dq, (ll)Sq*Dq, 0, (ll)Cq*Sq, Bq, ACT_NONE);
        softmax_k<<<MC, 256>>>(scr);
        gemm(0,0, scr, vb, 0, 0, att, Cq, Dq, Sq, Sq, Dq, Dq, 0,
             (ll)Cq*Sq, (ll)Sq*Dq, 0, (ll)Cq*Dq, Bq, ACT_NONE);
        gemm(0,0, att, w_attn_out, 0, seg, yt, MC, Dq, Dq, Dq, Dq, Dq, Dq, 0,0,0,0, 1, ACT_NONE);

        // memory update: kk, vv; forward; grads; momentum update
        gemm(0,0, yt, mem_wk, 0, 0, kk, MC, Dq, Dq, Dq, Dq, Dq, 0, 0,0,0,0, 1, ACT_NONE);
        gemm(0,0, yt, mem_wv, 0, 0, vv, MC, Dq, Dq, Dq, Dq, Dq, 0, 0,0,0,0, 1, ACT_NONE);
        gemm(0,0, kk, W0p, B0p, 0, pre, MC, Hq, Dq, Dq, Hq, Hq, 0, 0,0,0,0, 1, ACT_NONE);
        silu_k<<<blks(L_MCH), 256>>>(hsil, pre, L_MCH);
        gemm(0,0, hsil, W1p, B1p, 0, ym, MC, Dq, Hq, Hq, Dq, Dq, 0, 0,0,0,0, 1, ACT_NONE);
        e_k<<<blks(L_MCD), 256>>>(eb, ym, vv, L_MCD);
        // gw1 = hsil^T @ e
        gemm(1,0, hsil, eb, 0, 0, gw1, Hq, Dq, MC, Hq, Dq, Dq, 0, 0,0,0,0, 1, ACT_NONE);
        colsum_k<<<(Dq+255)/256, 256>>>(gb1, eb, MC, Dq);
        // dh = e @ w1^T ; dpre = dh * silu'(pre)
        gemm(0,1, eb, W1p, 0, 0, dh, MC, Hq, Dq, Dq, Dq, Hq, 0, 0,0,0,0, 1, ACT_NONE);
        dsilu_k<<<blks(L_MCH), 256>>>(dh, pre, L_MCH);
        // gw0 = kk^T @ dpre
        gemm(1,0, kk, dh, 0, 0, gw0, Dq, Hq, MC, Dq, Hq, Hq, 0, 0,0,0,0, 1, ACT_NONE);
        colsum_k<<<(Hq+255)/256, 256>>>(gb0, dh, MC, Hq);
        update_k<<<blks(L_W0), 256>>>(W0p, M0p, gw0, L_W0);
        update_k<<<blks(Hq), 256>>>(B0p, MB0p, gb0, Hq);
        update_k<<<blks(L_W0), 256>>>(W1p, M1p, gw1, L_W0);
        update_k<<<blks(Dq), 256>>>(B1p, MB1p, gb1, Dq);

        // mem_out with updated memory
        gemm(0,0, yt, wq_ctx, 0, 0, qn, MC, Dq, Dq, Dq, Dq, Dq, 0, 0,0,0,0, 1, ACT_NONE);
        l2norm_k<<<MC, 256>>>(qn, 1.0f);
        gemm(0,0, qn, W0p, B0p, 0, hsil, MC, Hq, Dq, Dq, Hq, Hq, 0, 0,0,0,0, 1, ACT_SILU);
        gemm(0,0, hsil, W1p, B1p, 0, mo, MC, Dq, Hq, Hq, Dq, Dq, 0, 0,0,0,0, 1, ACT_NONE);

        // gate + combine
        ln_k<<<MC, 256>>>(yt, lny, gate_g, gate_b);
        gemm(0,0, lny, w_gate, 0, 0, gate, MC, Dq, Dq, Dq, Dq, Dq, 0, 0,0,0,0, 1, ACT_SIG);
        combine_k<<<blks(L_MCD), 256>>>(ob, yt, gate, mo, L_MCD);

        // FFN with residual, write directly to output slice
        ln_k<<<MC, 256>>>(ob, lny, n2_g, n2_b);
        gemm(0,0, lny, ffn_w1, ffn_b1, 0, ffh, MC, FFNq, Dq, Dq, FFNq, FFNq, 0,
             0,0,0,0, 1, ACT_SILU);
        gemm(0,0, ffh, ffn_w2, ffn_b2, ob, out + (ll)ch*Cq*Dq, Cq, Dq, FFNq,
             FFNq, Dq, Dq, Dq, (ll)Cq*FFNq, 0, (ll)Cq*Dq, (ll)Tq*Dq, Bq, ACT_NONE);
    }
}

// round 5
// speedup vs baseline: 1.3558x; 1.3558x over previous
#include <cuda_runtime.h>
#include <cuda_bf16.h>
#include <cstdint>

#define Bq 2
#define Tq 4096
#define Dq 1024
#define Cq 512
#define Pq 16
#define Hq 2048
#define FFNq 4096
#define Sq (Pq + 2*Cq)          // 1040
#define MC (Bq*Cq)              // 1024
#define MS (Bq*Sq)              // 2080
#define NCHUNK (Tq/Cq)          // 8

#define ACT_NONE 0
#define ACT_SILU 1
#define ACT_SIG  2

typedef long long ll;
static const ll L_MCD = (ll)MC*Dq;
static const ll L_MCH = (ll)MC*Hq;
static const ll L_MSD = (ll)MS*Dq;
static const ll L_W0  = (ll)Dq*Hq;
static const ll L_DD  = (ll)Dq*Dq;

// ---------------- scratch layout ----------------
#define O_SEG  0LL
#define O_QN   (O_SEG  + (ll)MC*Dq)
#define O_PRE  (O_QN   + (ll)MC*Dq)
#define O_HSIL (O_PRE  + (ll)MC*Hq)
#define O_H    (O_HSIL + (ll)MC*Hq)
#define O_AUG  (O_H    + (ll)MC*Dq)
#define O_LN   (O_AUG  + (ll)MS*Dq)
#define O_Q    (O_LN   + (ll)MS*Dq)
#define O_K    (O_Q    + (ll)MC*Dq)
#define O_V    (O_K    + (ll)MS*Dq)
#define O_SCR  (O_V    + (ll)MS*Dq)
#define O_ATT  (O_SCR  + (ll)MC*Sq)
#define O_YT   (O_ATT  + (ll)MC*Dq)
#define O_KK   (O_YT   + (ll)MC*Dq)
#define O_VV   (O_KK   + (ll)MC*Dq)
#define O_YM   (O_VV   + (ll)MC*Dq)
#define O_E    (O_YM   + (ll)MC*Dq)
#define O_DH   (O_E    + (ll)MC*Dq)
#define O_GW0  (O_DH   + (ll)MC*Hq)
#define O_GW1  (O_GW0  + (ll)Dq*Hq)
#define O_GB0  (O_GW1  + (ll)Hq*Dq)
#define O_GB1  (O_GB0  + Hq)
#define O_W0   (O_GB1  + Dq)
#define O_B0   (O_W0   + (ll)Dq*Hq)
#define O_W1   (O_B0   + Hq)
#define O_B1   (O_W1   + (ll)Hq*Dq)
#define O_M0   (O_B1   + Dq)
#define O_MB0  (O_M0   + (ll)Dq*Hq)
#define O_M1   (O_MB0  + Hq)
#define O_MB1  (O_M1   + (ll)Hq*Dq)
#define O_MO   (O_MB1  + Dq)
#define O_LNY  (O_MO   + (ll)MC*Dq)
#define O_GATE (O_LNY  + (ll)MC*Dq)
#define O_O    (O_GATE + (ll)MC*Dq)
#define O_FFH  (O_O    + (ll)MC*Dq)
#define O_TQC  (O_FFH  + (ll)MC*FFNq)
#define O_TQ   (O_TQC  + L_DD)
#define O_TK   (O_TQ   + L_DD)
#define O_TV   (O_TK   + L_DD)
#define O_TAO  (O_TV   + L_DD)
#define O_TG   (O_TAO  + L_DD)
#define O_TF1  (O_TG   + L_DD)
#define O_TF2  (O_TF1  + (ll)Dq*FFNq)
#define O_TMK  (O_TF2  + (ll)FFNq*Dq)
#define O_TMV  (O_TMK  + L_DD)
#define O_W0T  (O_TMV  + L_DD)
#define O_W1T  (O_W0T  + (ll)Hq*Dq)
#define O_VBT  (O_W1T  + (ll)Dq*Hq)
#define O_HST  (O_VBT  + (ll)Bq*Dq*Sq)
#define O_ET   (O_HST  + (ll)Hq*MC)
#define O_KKT  (O_ET   + (ll)Dq*MC)
#define O_DHT  (O_KKT  + (ll)Dq*MC)
#define O_CS   (O_DHT  + (ll)Hq*MC)
#define O_END  (O_CS   + 16LL*4096)

__device__ float g_buf[O_END];

// ================= mma.sync bf16 GEMM (family-target safe) =================
// C(M,N) = act( A(M,K) @ Bn(N,K)^T + bias ) + R
// fp32 operands split to bf16 hi/lo; 3 products: AhBh + AhBl + AlBh.

#define LDH 40                    // halfs per smem row (32 data + 8 pad)
#define PLANE_H (128*LDH)         // 5120 halfs per plane
#define STG_H   (4*PLANE_H)       // Ah Al Bh Bl
#define MM_SMEM (2*STG_H*2)       // 81920 bytes (2 stages)

__device__ __forceinline__ uint32_t smem_u32(const void* p) {
    uint32_t a;
    asm("{ .reg .u64 t; cvta.to.shared.u64 t, %1; cvt.u32.u64 %0, t; }" : "=r"(a) : "l"(p));
    return a;
}
__device__ __forceinline__ void ldm_x4(uint32_t* r, uint32_t addr) {
    asm volatile("ldmatrix.sync.aligned.m8n8.x4.shared.b16 {%0,%1,%2,%3}, [%4];"
        : "=r"(r[0]), "=r"(r[1]), "=r"(r[2]), "=r"(r[3]) : "r"(addr));
}
__device__ __forceinline__ void ldm_x2(uint32_t* r, uint32_t addr) {
    asm volatile("ldmatrix.sync.aligned.m8n8.x2.shared.b16 {%0,%1}, [%2];"
        : "=r"(r[0]), "=r"(r[1]) : "r"(addr));
}
__device__ __forceinline__ void mma_bf16(float* d, const uint32_t* a, const uint32_t* b) {
    asm volatile(
        "mma.sync.aligned.m16n8k16.row.col.f32.bf16.bf16.f32 "
        "{%0,%1,%2,%3}, {%4,%5,%6,%7}, {%8,%9}, {%0,%1,%2,%3};"
        : "+f"(d[0]), "+f"(d[1]), "+f"(d[2]), "+f"(d[3])
        : "r"(a[0]), "r"(a[1]), "r"(a[2]), "r"(a[3]), "r"(b[0]), "r"(b[1]));
}

__device__ __forceinline__ void ld_tile(
    const float* __restrict__ src, int ld, int row0, int rowlim, int k0, int K, float4* reg)
{
    int tid = threadIdx.x;
    int c4 = tid & 7, rb = tid >> 3;
#pragma unroll
    for (int s = 0; s < 4; s++) {
        int row = s*32 + rb;
        int grow = row0 + row;
        float4 v = make_float4(0.f,0.f,0.f,0.f);
        int gk = k0 + c4*4;
        if (grow < rowlim) {
            const float* p = src + (ll)grow * ld + gk;
            if (gk + 3 < K) v = *(const float4*)p;
            else {
                if (gk   < K) v.x = p[0];
                if (gk+1 < K) v.y = p[1];
                if (gk+2 < K) v.z = p[2];
                if (gk+3 < K) v.w = p[3];
            }
        }
        reg[s] = v;
    }
}

__device__ __forceinline__ void st_split(
    __nv_bfloat16* hi, __nv_bfloat16* lo, const float4* reg)
{
    int tid = threadIdx.x;
    int c4 = tid & 7, rb = tid >> 3;
#pragma unroll
    for (int s = 0; s < 4; s++) {
        int row = s*32 + rb;
        float4 v = reg[s];
        __nv_bfloat16 h0 = __float2bfloat16(v.x);
        __nv_bfloat16 h1 = __float2bfloat16(v.y);
        __nv_bfloat16 h2 = __float2bfloat16(v.z);
        __nv_bfloat16 h3 = __float2bfloat16(v.w);
        __nv_bfloat16 l0 = __float2bfloat16(v.x - __bfloat162float(h0));
        __nv_bfloat16 l1 = __float2bfloat16(v.y - __bfloat162float(h1));
        __nv_bfloat16 l2 = __float2bfloat16(v.z - __bfloat162float(h2));
        __nv_bfloat16 l3 = __float2bfloat16(v.w - __bfloat162float(h3));
        ushort4 hp, lp;
        hp.x = __bfloat16_as_ushort(h0); hp.y = __bfloat16_as_ushort(h1);
        hp.z = __bfloat16_as_ushort(h2); hp.w = __bfloat16_as_ushort(h3);
        lp.x = __bfloat16_as_ushort(l0); lp.y = __bfloat16_as_ushort(l1);
        lp.z = __bfloat16_as_ushort(l2); lp.w = __bfloat16_as_ushort(l3);
        *(ushort4*)(hi + row*LDH + c4*4) = hp;
        *(ushort4*)(lo + row*LDH + c4*4) = lp;
    }
}

__global__ void __launch_bounds__(256, 1)
mm_gemm_k(const float* __restrict__ A, const float* __restrict__ Bn,
          const float* __restrict__ bias, const float* __restrict__ R,
          float* __restrict__ Cc,
          int M, int N, int K, int lda, int ldb, int ldc, int ldr,
          ll sA, ll sB, ll sR, ll sC, int act)
{
    extern __shared__ __nv_bfloat16 sm[];
    int tid = threadIdx.x;
    int bz  = blockIdx.z;
    A  += (ll)bz * sA;
    Bn += (ll)bz * sB;
    Cc += (ll)bz * sC;
    const float* Rp = R ? (R + (ll)bz * sR) : (const float*)0;
    int row0 = blockIdx.y * 128;
    int col0 = blockIdx.x * 128;

    int w = tid >> 5, l = tid & 31;
    int wm = w & 1, wn = w >> 1;        // warp tile: 64(m) x 32(n)

    float acc[4][4][4];
#pragma unroll
    for (int a = 0; a < 4; a++)
#pragma unroll
        for (int b = 0; b < 4; b++)
#pragma unroll
            for (int c = 0; c < 4; c++) acc[a][b][c] = 0.f;

    float4 ra[4], rb4[4];
    int nk = (K + 31) / 32;

    ld_tile(A,  lda, row0, M, 0, K, ra);
    ld_tile(Bn, ldb, col0, N, 0, K, rb4);
    st_split(sm,             sm + PLANE_H,   ra);
    st_split(sm + 2*PLANE_H, sm + 3*PLANE_H, rb4);
    __syncthreads();

    uint32_t sb0 = smem_u32(sm);

    // per-lane ldmatrix addresses (within a plane, in halfs)
    int a_row = (l & 15);
    int a_kc  = (l >> 4) * 8;
    int b_row = (l & 7);
    int b_kc  = ((l >> 3) & 1) * 8;

    for (int i = 0; i < nk; i++) {
        int cur = i & 1;
        if (i + 1 < nk) {
            ld_tile(A,  lda, row0, M, (i+1)*32, K, ra);
            ld_tile(Bn, ldb, col0, N, (i+1)*32, K, rb4);
        }
        uint32_t base = sb0 + (uint32_t)cur * STG_H * 2;
#pragma unroll
        for (int kh = 0; kh < 32; kh += 16) {
            uint32_t Ah[4][4], Al[4][4], Bh[4][2], Bl[4][2];
#pragma unroll
            for (int mg = 0; mg < 4; mg++) {
                int mrow = wm*64 + mg*16 + a_row;
                uint32_t ad = base + (uint32_t)(mrow*LDH + kh + a_kc) * 2;
                ldm_x4(Ah[mg], ad);
                ldm_x4(Al[mg], ad + PLANE_H*2);
            }
#pragma unroll
            for (int ng = 0; ng < 4; ng++) {
                int nrow = wn*32 + ng*8 + b_row;
                uint32_t bd = base + (uint32_t)(2*PLANE_H + nrow*LDH + kh + b_kc) * 2;
                ldm_x2(Bh[ng], bd);
                ldm_x2(Bl[ng], bd + PLANE_H*2);
            }
#pragma unroll
            for (int mg = 0; mg < 4; mg++)
#pragma unroll
                for (int ng = 0; ng < 4; ng++) {
                    mma_bf16(acc[mg][ng], Ah[mg], Bh[ng]);
                    mma_bf16(acc[mg][ng], Ah[mg], Bl[ng]);
                    mma_bf16(acc[mg][ng], Al[mg], Bh[ng]);
                }
        }
        if (i + 1 < nk) {
            int nxt = (i + 1) & 1;
            __nv_bfloat16* ns = sm + (ll)nxt * STG_H;
            st_split(ns,             ns + PLANE_H,   ra);
            st_split(ns + 2*PLANE_H, ns + 3*PLANE_H, rb4);
            __syncthreads();
        }
    }

    // ---- epilogue ----
    int mbase = row0 + wm*64;
    int nbase = col0 + wn*32;
#pragma unroll
    for (int mg = 0; mg < 4; mg++) {
#pragma unroll
        for (int ng = 0; ng < 4; ng++) {
            int cc = nbase + ng*8 + (l & 3)*2;
#pragma unroll
            for (int h2 = 0; h2 < 2; h2++) {
                int r = mbase + mg*16 + (l >> 2) + h2*8;
                if (r < M && cc < N) {
                    float o0 = acc[mg][ng][h2*2+0];
                    float o1 = acc[mg][ng][h2*2+1];
                    if (bias) { o0 += bias[cc]; o1 += bias[cc+1]; }
                    if (act == ACT_SILU) {
                        o0 *= 1.f/(1.f+__expf(-o0));
                        o1 *= 1.f/(1.f+__expf(-o1));
                    } else if (act == ACT_SIG) {
                        o0 = 1.f/(1.f+__expf(-o0));
                        o1 = 1.f/(1.f+__expf(-o1));
                    }
                    if (Rp) {
                        float2 rr = *(const float2*)(Rp + (ll)r * ldr + cc);
                        o0 += rr.x; o1 += rr.y;
                    }
                    float2 ov; ov.x = o0; ov.y = o1;
                    *(float2*)(Cc + (ll)r * ldc + cc) = ov;
                }
            }
        }
    }
}

// ---------------- transpose: in(R,C) -> out(C,R) ----------------
__global__ void tr_k(const float* __restrict__ in, float* __restrict__ out,
                     int R, int Cn, ll sIn, ll sOut)
{
    __shared__ float t[32][33];
    in  += (ll)blockIdx.z * sIn;
    out += (ll)blockIdx.z * sOut;
    int c0 = blockIdx.x * 32, r0 = blockIdx.y * 32;
    int x = threadIdx.x, y = threadIdx.y;   // (32, 8)
#pragma unroll
    for (int j = 0; j < 4; j++) {
        int r = r0 + y + 8*j;
        if (r < R && c0 + x < Cn) t[y + 8*j][x] = in[(ll)r * Cn + c0 + x];
    }
    __syncthreads();
#pragma unroll
    for (int j = 0; j < 4; j++) {
        int c = c0 + y + 8*j;
        int r = r0 + x;
        if (c < Cn && r < R) out[(ll)c * R + r] = t[x][y + 8*j];
    }
}

// ---------------- elementwise / reduction kernels ----------------
__global__ void seg_k(float* __restrict__ seg, const float* __restrict__ x, int ch)
{
    ll i = (ll)blockIdx.x * blockDim.x + threadIdx.x;
    if (i >= L_MCD) return;
    int d = (int)(i % Dq);
    ll row = i / Dq;
    int b = (int)(row / Cq), t = (int)(row % Cq);
    seg[i] = x[((ll)b*Tq + (ll)ch*Cq + t) * Dq + d];
}

__global__ void aug_k(float* __restrict__ aug, const float* __restrict__ pers,
                      const float* __restrict__ h, const float* __restrict__ seg)
{
    ll i = (ll)blockIdx.x * blockDim.x + threadIdx.x;
    if (i >= L_MSD) return;
    int d = (int)(i % Dq);
    ll row = i / Dq;
    int b = (int)(row / Sq), s = (int)(row % Sq);
    float v;
    if (s < Pq)            v = pers[(ll)s*Dq + d];
    else if (s < Pq+Cq)    v = h[((ll)b*Cq + (s-Pq)) * Dq + d];
    else                   v = seg[((ll)b*Cq + (s-Pq-Cq)) * Dq + d];
    aug[i] = v;
}

__global__ void l2norm_k(float* __restrict__ x, float scale)
{
    ll row = blockIdx.x;
    float* p = x + row * Dq;
    __shared__ float red[256];
    int t = threadIdx.x;
    float s = 0.f;
    for (int j = t; j < Dq; j += 256) { float v = p[j]; s += v*v; }
    red[t] = s; __syncthreads();
    for (int k = 128; k > 0; k >>= 1) { if (t < k) red[t] += red[t+k]; __syncthreads(); }
    float inv = scale / fmaxf(sqrtf(red[0]), 1e-12f);
    for (int j = t; j < Dq; j += 256) p[j] *= inv;
}

__global__ void ln_k(const float* __restrict__ src, float* __restrict__ dst,
                     const float* __restrict__ g, const float* __restrict__ b)
{
    ll row = blockIdx.x;
    const float* p = src + row * Dq;
    float* q = dst + row * Dq;
    __shared__ float red[256];
    int t = threadIdx.x;
    float s = 0.f;
    for (int j = t; j < Dq; j += 256) s += p[j];
    red[t] = s; __syncthreads();
    for (int k = 128; k > 0; k >>= 1) { if (t < k) red[t] += red[t+k]; __syncthreads(); }
    float mean = red[0] / (float)Dq;
    __syncthreads();
    float vs = 0.f;
    for (int j = t; j < Dq; j += 256) { float d = p[j] - mean; vs += d*d; }
    red[t] = vs; __syncthreads();
    for (int k = 128; k > 0; k >>= 1) { if (t < k) red[t] += red[t+k]; __syncthreads(); }
    float inv = rsqrtf(red[0] / (float)Dq + 1e-5f);
    for (int j = t; j < Dq; j += 256) q[j] = (p[j] - mean) * inv * g[j] + b[j];
}

__global__ void softmax_k(float* __restrict__ sc)
{
    ll row = blockIdx.x;               // 0..MC-1 (b*Cq + qi)
    int qi = (int)(row % Cq);
    float* p = sc + row * Sq;
    int L = Pq + Cq + qi + 1;
    __shared__ float red[256];
    int t = threadIdx.x;
    float mx = -1e30f;
    for (int j = t; j < L; j += 256) mx = fmaxf(mx, p[j]);
    red[t] = mx; __syncthreads();
    for (int k = 128; k > 0; k >>= 1) { if (t < k) red[t] = fmaxf(red[t], red[t+k]); __syncthreads(); }
    mx = red[0]; __syncthreads();
    float sum = 0.f;
    for (int j = t; j < L; j += 256) { float e = __expf(p[j] - mx); p[j] = e; sum += e; }
    red[t] = sum; __syncthreads();
    for (int k = 128; k > 0; k >>= 1) { if (t < k) red[t] += red[t+k]; __syncthreads(); }
    float inv = 1.f / red[0];
    for (int j = t; j < L; j += 256) p[j] *= inv;
    for (int j = L + t; j < Sq; j += 256) p[j] = 0.f;
}

__global__ void silu_k(float* __restrict__ dst, const float* __restrict__ src, ll n)
{
    ll i = (ll)blockIdx.x * blockDim.x + threadIdx.x;
    if (i >= n) return;
    float z = src[i];
    dst[i] = z / (1.f + __expf(-z));
}

__global__ void e_k(float* __restrict__ e, const float* __restrict__ ym,
                    const float* __restrict__ vv, ll n)
{
    ll i = (ll)blockIdx.x * blockDim.x + threadIdx.x;
    if (i >= n) return;
    e[i] = (ym[i] - vv[i]) * (1.f / (float)MC);
}

__global__ void dsilu_k(float* __restrict__ dh, const float* __restrict__ pre, ll n)
{
    ll i = (ll)blockIdx.x * blockDim.x + threadIdx.x;
    if (i >= n) return;
    float z = pre[i];
    float s = 1.f / (1.f + __expf(-z));
    dh[i] *= s * (1.f + z * (1.f - s));
}

// deterministic split-row column sum
__global__ void colsum1_k(float* __restrict__ part, const float* __restrict__ src, int Mr, int N)
{
    int c = blockIdx.x * blockDim.x + threadIdx.x;
    if (c >= N) return;
    int r0 = blockIdx.y * 64;
    int r1 = min(r0 + 64, Mr);
    float s = 0.f;
    for (int r = r0; r < r1; r++) s += src[(ll)r * N + c];
    part[(ll)blockIdx.y * N + c] = s;
}
__global__ void colsum2_k(float* __restrict__ dst, const float* __restrict__ part, int ny, int N)
{
    int c = blockIdx.x * blockDim.x + threadIdx.x;
    if (c >= N) return;
    float s = 0.f;
    for (int r = 0; r < ny; r++) s += part[(ll)r * N + c];
    dst[c] = s;
}

__global__ void update_k(float* __restrict__ p, float* __restrict__ m,
                         const float* __restrict__ g, ll n)
{
    ll i = (ll)blockIdx.x * blockDim.x + threadIdx.x;
    if (i >= n) return;
    float mm = 0.9f * m[i] + g[i];
    m[i] = mm;
    p[i] = 0.99f * p[i] - 0.01f * mm;
}

__global__ void combine_k(float* __restrict__ o, const float* __restrict__ yt,
                          const float* __restrict__ gate, const float* __restrict__ mo, ll n)
{
    ll i = (ll)blockIdx.x * blockDim.x + threadIdx.x;
    if (i >= n) return;
    float g = gate[i];
    o[i] = yt[i] * g + mo[i] * (1.f - g);
}

// ---------------- host helpers ----------------
static inline int blks(ll n) { return (int)((n + 255) / 256); }

static void tc_gemm(const float* A, const float* Bn, const float* bias, const float* R, float* C,
                    int M, int N, int K, int lda, int ldb, int ldc, int ldr,
                    ll sA, ll sB, ll sR, ll sC, int batch, int act)
{
    dim3 grid((N + 127) / 128, (M + 127) / 128, batch);
    mm_gemm_k<<<grid, 256, MM_SMEM>>>(A, Bn, bias, R, C, M, N, K, lda, ldb, ldc, ldr,
                                      sA, sB, sR, sC, act);
}

static void transpose(const float* in, float* out, int R, int C_, ll sIn = 0, ll sOut = 0, int batch = 1)
{
    dim3 g((C_ + 31) / 32, (R + 31) / 32, batch);
    tr_k<<<g, dim3(32, 8)>>>(in, out, R, C_, sIn, sOut);
}

static void colsum(float* dst, float* part, const float* src, int Mr, int N)
{
    int ny = (Mr + 63) / 64;
    dim3 g1((N + 255) / 256, ny);
    colsum1_k<<<g1, 256>>>(part, src, Mr, N);
    colsum2_k<<<(N + 255) / 256, 256>>>(dst, part, ny, N);
}

extern "C" void kernel_launch(void* const* d_in, const int* in_sizes, int n_in,
                              void* d_out, int out_size)
{
    (void)in_sizes; (void)n_in; (void)out_size;
    const float* x         = (const float*)d_in[0];
    const float* wq_ctx    = (const float*)d_in[1];
    const float* wq        = (const float*)d_in[2];
    const float* wk        = (const float*)d_in[3];
    const float* wv        = (const float*)d_in[4];
    const float* w_attn_out= (const float*)d_in[5];
    const float* w_gate    = (const float*)d_in[6];
    const float* gate_g    = (const float*)d_in[7];
    const float* gate_b    = (const float*)d_in[8];
    const float* n1_g      = (const float*)d_in[9];
    const float* n1_b      = (const float*)d_in[10];
    const float* n2_g      = (const float*)d_in[11];
    const float* n2_b      = (const float*)d_in[12];
    const float* ffn_w1    = (const float*)d_in[13];
    const float* ffn_b1    = (const float*)d_in[14];
    const float* ffn_w2    = (const float*)d_in[15];
    const float* ffn_b2    = (const float*)d_in[16];
    const float* pers      = (const float*)d_in[17];
    const float* mem_w0    = (const float*)d_in[18];
    const float* mem_b0    = (const float*)d_in[19];
    const float* mem_w1    = (const float*)d_in[20];
    const float* mem_b1    = (const float*)d_in[21];
    const float* mem_wk    = (const float*)d_in[22];
    const float* mem_wv    = (const float*)d_in[23];
    float* out = (float*)d_out;

    cudaFuncSetAttribute(mm_gemm_k, cudaFuncAttributeMaxDynamicSharedMemorySize, MM_SMEM);

    float* base;
    cudaGetSymbolAddress((void**)&base, g_buf);

    float* seg  = base + O_SEG;   float* qn   = base + O_QN;
    float* pre  = base + O_PRE;   float* hsil = base + O_HSIL;
    float* hbuf = base + O_H;     float* aug  = base + O_AUG;
    float* lnag = base + O_LN;    float* qb   = base + O_Q;
    float* kb   = base + O_K;     float* vb   = base + O_V;
    float* scr  = base + O_SCR;   float* att  = base + O_ATT;
    float* yt   = base + O_YT;    float* kk   = base + O_KK;
    float* vv   = base + O_VV;    float* ym   = base + O_YM;
    float* eb   = base + O_E;     float* dh   = base + O_DH;
    float* gw0  = base + O_GW0;   float* gw1  = base + O_GW1;
    float* gb0  = base + O_GB0;   float* gb1  = base + O_GB1;
    float* W0p  = base + O_W0;    float* B0p  = base + O_B0;
    float* W1p  = base + O_W1;    float* B1p  = base + O_B1;
    float* M0p  = base + O_M0;    float* MB0p = base + O_MB0;
    float* M1p  = base + O_M1;    float* MB1p = base + O_MB1;
    float* mo   = base + O_MO;    float* lny  = base + O_LNY;
    float* gate = base + O_GATE;  float* ob   = base + O_O;
    float* ffh  = base + O_FFH;
    float* TQC  = base + O_TQC;   float* TQ   = base + O_TQ;
    float* TK   = base + O_TK;    float* TV   = base + O_TV;
    float* TAO  = base + O_TAO;   float* TG   = base + O_TG;
    float* TF1  = base + O_TF1;   float* TF2  = base + O_TF2;
    float* TMK  = base + O_TMK;   float* TMV  = base + O_TMV;
    float* W0T  = base + O_W0T;   float* W1T  = base + O_W1T;
    float* VBT  = base + O_VBT;   float* HST  = base + O_HST;
    float* ET   = base + O_ET;    float* KKT  = base + O_KKT;
    float* DHT  = base + O_DHT;   float* CS   = base + O_CS;

    // init memory state + zero momentum (every call: deterministic)
    cudaMemcpyAsync(W0p, mem_w0, L_W0 * sizeof(float), cudaMemcpyDeviceToDevice);
    cudaMemcpyAsync(B0p, mem_b0, Hq   * sizeof(float), cudaMemcpyDeviceToDevice);
    cudaMemcpyAsync(W1p, mem_w1, L_W0 * sizeof(float), cudaMemcpyDeviceToDevice);
    cudaMemcpyAsync(B1p, mem_b1, Dq   * sizeof(float), cudaMemcpyDeviceToDevice);
    cudaMemsetAsync(M0p,  0, L_W0 * sizeof(float));
    cudaMemsetAsync(MB0p, 0, Hq   * sizeof(float));
    cudaMemsetAsync(M1p,  0, L_W0 * sizeof(float));
    cudaMemsetAsync(MB1p, 0, Dq   * sizeof(float));

    // static weight transposes (K-major B operands): out(N,K)
    transpose(wq_ctx,     TQC, Dq, Dq);
    transpose(wq,         TQ,  Dq, Dq);
    transpose(wk,         TK,  Dq, Dq);
    transpose(wv,         TV,  Dq, Dq);
    transpose(w_attn_out, TAO, Dq, Dq);
    transpose(w_gate,     TG,  Dq, Dq);
    transpose(ffn_w1,     TF1, Dq, FFNq);
    transpose(ffn_w2,     TF2, FFNq, Dq);
    transpose(mem_wk,     TMK, Dq, Dq);
    transpose(mem_wv,     TMV, Dq, Dq);
    transpose(W0p, W0T, Dq, Hq);
    transpose(W1p, W1T, Hq, Dq);

    for (int ch = 0; ch < NCHUNK; ch++) {
        seg_k<<<blks(L_MCD), 256>>>(seg, x, ch);

        // h = mem_mlp(mem, l2norm(seg @ wq_ctx))
        tc_gemm(seg, TQC, 0, 0, qn, MC, Dq, Dq, Dq, Dq, Dq, 0, 0,0,0,0, 1, ACT_NONE);
        l2norm_k<<<MC, 256>>>(qn, 1.0f);
        tc_gemm(qn, W0T, B0p, 0, hsil, MC, Hq, Dq, Dq, Dq, Hq, 0, 0,0,0,0, 1, ACT_SILU);
        tc_gemm(hsil, W1T, B1p, 0, hbuf, MC, Dq, Hq, Hq, Hq, Dq, 0, 0,0,0,0, 1, ACT_NONE);

        aug_k<<<blks(L_MSD), 256>>>(aug, pers, hbuf, seg);
        ln_k<<<MS, 256>>>(aug, lnag, n1_g, n1_b);

        tc_gemm(lnag, TK, 0, 0, kb, MS, Dq, Dq, Dq, Dq, Dq, 0, 0,0,0,0, 1, ACT_NONE);
        l2norm_k<<<MS, 256>>>(kb, 1.0f);
        tc_gemm(lnag, TV, 0, 0, vb, MS, Dq, Dq, Dq, Dq, Dq, 0, 0,0,0,0, 1, ACT_NONE);
        tc_gemm(lnag + (ll)(Pq+Cq)*Dq, TQ, 0, 0, qb, Cq, Dq, Dq, Dq, Dq, Dq, 0,
                (ll)Sq*Dq, 0, 0, (ll)Cq*Dq, Bq, ACT_NONE);
        l2norm_k<<<MC, 256>>>(qb, 32.0f);   // * sqrt(D)

        // scores = q @ k^T  (kb already (n,k) per batch)
        tc_gemm(qb, kb, 0, 0, scr, Cq, Sq, Dq, Dq, Dq, Sq, 0,
                (ll)Cq*Dq, (ll)Sq*Dq, 0, (ll)Cq*Sq, Bq, ACT_NONE);
        softmax_k<<<MC, 256>>>(scr);
        transpose(vb, VBT, Sq, Dq, (ll)Sq*Dq, (ll)Dq*Sq, Bq);
        tc_gemm(scr, VBT, 0, 0, att, Cq, Dq, Sq, Sq, Sq, Dq, 0,
                (ll)Cq*Sq, (ll)Dq*Sq, 0, (ll)Cq*Dq, Bq, ACT_NONE);
        tc_gemm(att, TAO, 0, seg, yt, MC, Dq, Dq, Dq, Dq, Dq, Dq, 0,0,0,0, 1, ACT_NONE);

        // memory inner update
        tc_gemm(yt, TMK, 0, 0, kk, MC, Dq, Dq, Dq, Dq, Dq, 0, 0,0,0,0, 1, ACT_NONE);
        tc_gemm(yt, TMV, 0, 0, vv, MC, Dq, Dq, Dq, Dq, Dq, 0, 0,0,0,0, 1, ACT_NONE);
        tc_gemm(kk, W0T, B0p, 0, pre, MC, Hq, Dq, Dq, Dq, Hq, 0, 0,0,0,0, 1, ACT_NONE);
        silu_k<<<blks(L_MCH), 256>>>(hsil, pre, L_MCH);
        tc_gemm(hsil, W1T, B1p, 0, ym, MC, Dq, Hq, Hq, Hq, Dq, 0, 0,0,0,0, 1, ACT_NONE);
        e_k<<<blks(L_MCD), 256>>>(eb, ym, vv, L_MCD);
        transpose(hsil, HST, MC, Hq);
        transpose(eb,   ET,  MC, Dq);
        tc_gemm(HST, ET, 0, 0, gw1, Hq, Dq, MC, MC, MC, Dq, 0, 0,0,0,0, 1, ACT_NONE);
        colsum(gb1, CS, eb, MC, Dq);
        tc_gemm(eb, W1p, 0, 0, dh, MC, Hq, Dq, Dq, Dq, Hq, 0, 0,0,0,0, 1, ACT_NONE);
        dsilu_k<<<blks(L_MCH), 256>>>(dh, pre, L_MCH);
        transpose(kk, KKT, MC, Dq);
        transpose(dh, DHT, MC, Hq);
        tc_gemm(KKT, DHT, 0, 0, gw0, Dq, Hq, MC, MC, MC, Hq, 0, 0,0,0,0, 1, ACT_NONE);
        colsum(gb0, CS, dh, MC, Hq);
        update_k<<<blks(L_W0), 256>>>(W0p, M0p, gw0, L_W0);
        update_k<<<blks(Hq), 256>>>(B0p, MB0p, gb0, Hq);
        update_k<<<blks(L_W0), 256>>>(W1p, M1p, gw1, L_W0);
        update_k<<<blks(Dq), 256>>>(B1p, MB1p, gb1, Dq);
        transpose(W0p, W0T, Dq, Hq);
        transpose(W1p, W1T, Hq, Dq);

        // mem_out with updated memory
        tc_gemm(yt, TQC, 0, 0, qn, MC, Dq, Dq, Dq, Dq, Dq, 0, 0,0,0,0, 1, ACT_NONE);
        l2norm_k<<<MC, 256>>>(qn, 1.0f);
        tc_gemm(qn, W0T, B0p, 0, hsil, MC, Hq, Dq, Dq, Dq, Hq, 0, 0,0,0,0, 1, ACT_SILU);
        tc_gemm(hsil, W1T, B1p, 0, mo, MC, Dq, Hq, Hq, Hq, Dq, 0, 0,0,0,0, 1, ACT_NONE);

        // gate + combine
        ln_k<<<MC, 256>>>(yt, lny, gate_g, gate_b);
        tc_gemm(lny, TG, 0, 0, gate, MC, Dq, Dq, Dq, Dq, Dq, 0, 0,0,0,0, 1, ACT_SIG);
        combine_k<<<blks(L_MCD), 256>>>(ob, yt, gate, mo, L_MCD);

        // FFN with residual -> output slice
        ln_k<<<MC, 256>>>(ob, lny, n2_g, n2_b);
        tc_gemm(lny, TF1, ffn_b1, 0, ffh, MC, FFNq, Dq, Dq, Dq, FFNq, 0,
                0,0,0,0, 1, ACT_SILU);
        tc_gemm(ffh, TF2, ffn_b2, ob, out + (ll)ch*Cq*Dq, Cq, Dq, FFNq,
                FFNq, FFNq, Dq, Dq, (ll)Cq*FFNq, 0, (ll)Cq*Dq, (ll)Tq*Dq, Bq, ACT_NONE);
    }
}

// round 9
// speedup vs baseline: 2.8298x; 2.0872x over previous
#include <cuda_runtime.h>
#include <cuda_bf16.h>
#include <cstdint>

#define Bq 2
#define Tq 4096
#define Dq 1024
#define Cq 512
#define Pq 16
#define Hq 2048
#define FFNq 4096
#define Sq (Pq + 2*Cq)          // 1040
#define MC (Bq*Cq)              // 1024
#define MS (Bq*Sq)              // 2080
#define NCHUNK (Tq/Cq)          // 8

#define ACT_NONE 0
#define ACT_SILU 1
#define ACT_SIG  2

typedef long long ll;
static const ll L_MCD = (ll)MC*Dq;
static const ll L_MCH = (ll)MC*Hq;
static const ll L_MSD = (ll)MS*Dq;
static const ll L_W0  = (ll)Dq*Hq;
static const ll L_DD  = (ll)Dq*Dq;

// ---------------- fp32 scratch ----------------
#define F_SEG  0LL
#define F_QN   (F_SEG + L_MCD)
#define F_PRE  (F_QN + L_MCD)
#define F_HSIL (F_PRE + L_MCH)
#define F_H    (F_HSIL + L_MCH)
#define F_AUG  (F_H + L_MCD)
#define F_KB   (F_AUG + L_MSD)
#define F_VB   (F_KB + L_MSD)
#define F_QB   (F_VB + L_MSD)
#define F_SCR  (F_QB + L_MCD)
#define F_YT   (F_SCR + (ll)MC*Sq)
#define F_KK   (F_YT + L_MCD)
#define F_VV   (F_KK + L_MCD)
#define F_YM   (F_VV + L_MCD)
#define F_EB   (F_YM + L_MCD)
#define F_DH   (F_EB + L_MCD)
#define F_GW0  (F_DH + L_MCH)
#define F_GW1  (F_GW0 + L_W0)
#define F_GB0  (F_GW1 + L_W0)
#define F_GB1  (F_GB0 + Hq)
#define F_W0   (F_GB1 + Dq)
#define F_B0   (F_W0 + L_W0)
#define F_W1   (F_B0 + Hq)
#define F_B1   (F_W1 + L_W0)
#define F_M0   (F_B1 + Dq)
#define F_MB0  (F_M0 + L_W0)
#define F_M1   (F_MB0 + Hq)
#define F_MB1  (F_M1 + L_W0)
#define F_MO   (F_MB1 + Dq)
#define F_GATE (F_MO + L_MCD)
#define F_OB   (F_GATE + L_MCD)
#define F_CS   (F_OB + L_MCD)
#define F_END  (F_CS + 16LL*4096)

__device__ float g_f[F_END];

// ---------------- bf16 hi/lo arena (hi plane then lo plane per buffer) ----------------
#define BO_SEG  0LL
#define BO_QN   (BO_SEG + 2*L_MCD)
#define BO_HSIL (BO_QN + 2*L_MCD)
#define BO_LNAG (BO_HSIL + 2*L_MCH)
#define BO_KB   (BO_LNAG + 2*L_MSD)
#define BO_QB   (BO_KB + 2*L_MSD)
#define BO_VBT  (BO_QB + 2*L_MCD)
#define BO_SCR  (BO_VBT + 2*L_MSD)
#define BO_ATT  (BO_SCR + 2*(ll)MC*Sq)
#define BO_YT   (BO_ATT + 2*L_MCD)
#define BO_KK   (BO_YT + 2*L_MCD)
#define BO_KKT  (BO_KK + 2*L_MCD)
#define BO_EB   (BO_KKT + 2*L_MCD)
#define BO_EBT  (BO_EB + 2*L_MCD)
#define BO_HST  (BO_EBT + 2*L_MCD)
#define BO_DHT  (BO_HST + 2*L_MCH)
#define BO_LNY  (BO_DHT + 2*L_MCH)
#define BO_FFH  (BO_LNY + 2*L_MCD)
#define BO_W0T  (BO_FFH + 2*(ll)MC*FFNq)
#define BO_W1T  (BO_W0T + 2*L_W0)
#define BO_W1N  (BO_W1T + 2*L_W0)
#define BO_TQC  (BO_W1N + 2*L_W0)
#define BO_TQ   (BO_TQC + 2*L_DD)
#define BO_TK   (BO_TQ + 2*L_DD)
#define BO_TV   (BO_TK + 2*L_DD)
#define BO_TAO  (BO_TV + 2*L_DD)
#define BO_TG   (BO_TAO + 2*L_DD)
#define BO_TMK  (BO_TG + 2*L_DD)
#define BO_TMV  (BO_TMK + 2*L_DD)
#define BO_TF1  (BO_TMV + 2*L_DD)
#define BO_TF2  (BO_TF1 + 2*(ll)Dq*FFNq)
#define BO_BEND (BO_TF2 + 2*(ll)Dq*FFNq)

__device__ __nv_bfloat16 g_b[BO_BEND];

// ================= low-level helpers =================
__device__ __forceinline__ uint32_t smem_u32(const void* p) {
    uint32_t a;
    asm("{ .reg .u64 t; cvta.to.shared.u64 t, %1; cvt.u32.u64 %0, t; }" : "=r"(a) : "l"(p));
    return a;
}
#define CP16(dst, src, n) \
    asm volatile("cp.async.cg.shared.global [%0], [%1], 16, %2;" \
        :: "r"(dst), "l"(src), "r"(n) : "memory")
#define CP_COMMIT() asm volatile("cp.async.commit_group;" ::: "memory")
#define CP_WAIT(n)  asm volatile("cp.async.wait_group %0;" :: "n"(n) : "memory")

__device__ __forceinline__ void ldm_x4(uint32_t* r, uint32_t addr) {
    asm volatile("ldmatrix.sync.aligned.m8n8.x4.shared.b16 {%0,%1,%2,%3}, [%4];"
        : "=r"(r[0]), "=r"(r[1]), "=r"(r[2]), "=r"(r[3]) : "r"(addr));
}
__device__ __forceinline__ void ldm_x2(uint32_t* r, uint32_t addr) {
    asm volatile("ldmatrix.sync.aligned.m8n8.x2.shared.b16 {%0,%1}, [%2];"
        : "=r"(r[0]), "=r"(r[1]) : "r"(addr));
}
__device__ __forceinline__ void mma_bf16(float* d, const uint32_t* a, const uint32_t* b) {
    asm volatile(
        "mma.sync.aligned.m16n8k16.row.col.f32.bf16.bf16.f32 "
        "{%0,%1,%2,%3}, {%4,%5,%6,%7}, {%8,%9}, {%0,%1,%2,%3};"
        : "+f"(d[0]), "+f"(d[1]), "+f"(d[2]), "+f"(d[3])
        : "r"(a[0]), "r"(a[1]), "r"(a[2]), "r"(a[3]), "r"(b[0]), "r"(b[1]));
}

__device__ __forceinline__ void split_store(__nv_bfloat16* b, ll e, ll i, float v) {
    __nv_bfloat16 h = __float2bfloat16(v);
    b[i] = h;
    b[e + i] = __float2bfloat16(v - __bfloat162float(h));
}

// ================= bf16 hi/lo GEMM via mma.sync + cp.async =================
// C(M,N)=act(A@B^T+bias)+R, A:(M,K) row-major, B:(N,K) K-major, both split hi/lo.
// Template BN in {128, 64}.  BM=128, BK=32, 3-stage cp.async pipeline.

template<int BN>
__global__ void __launch_bounds__(256, 1)
g3_k(const __nv_bfloat16* __restrict__ Ab, ll aE,
     const __nv_bfloat16* __restrict__ Bb, ll bE,
     const float* __restrict__ bias, const float* __restrict__ R,
     float* __restrict__ Cc, __nv_bfloat16* __restrict__ Ob, ll oE,
     int M, int N, int K, int lda, int ldb, int ldc, int ldr,
     ll sA, ll sB, ll sR, ll sC, int act)
{
    constexpr int SA_AL = 128*40;
    constexpr int SB_H  = 2*128*40;
    constexpr int SB_L  = SB_H + BN*40;
    constexpr int STG   = SB_L + BN*40;   // halfs per stage
    constexpr int PIPE  = 3;
    constexpr int WM    = (BN == 128) ? 2 : 4;
    constexpr int WTM   = 128 / WM;
    constexpr int MG    = WTM / 16;

    extern __shared__ __nv_bfloat16 sm[];
    uint32_t sb0 = smem_u32(sm);
    int tid = threadIdx.x;
    int bz = blockIdx.z;
    const __nv_bfloat16* A_h = Ab + (ll)bz * sA;
    const __nv_bfloat16* A_l = A_h + aE;
    const __nv_bfloat16* B_h = Bb + (ll)bz * sB;
    const __nv_bfloat16* B_l = B_h + bE;
    int row0 = blockIdx.y * 128;
    int col0 = blockIdx.x * BN;

    float acc[MG][4][4];
#pragma unroll
    for (int a = 0; a < MG; a++)
#pragma unroll
        for (int b = 0; b < 4; b++)
#pragma unroll
            for (int c = 0; c < 4; c++) acc[a][b][c] = 0.f;

    auto load_stage = [&](int slot, int k0) {
        uint32_t base = sb0 + (uint32_t)slot * STG * 2;
        for (int a2 = tid; a2 < 1024; a2 += 256) {
            int p = a2 >> 9, rem = a2 & 511;
            int row = rem >> 2, c16 = (rem & 3) * 8;
            int gr = row0 + row, gk = k0 + c16;
            int nb = 0;
            if (gr < M && gk < K) { nb = K - gk; if (nb > 8) nb = 8; }
            if (gr >= M) gr = row0;
            if (gk >= K) gk = 0;
            const __nv_bfloat16* src = (p ? A_l : A_h) + (ll)gr * lda + gk;
            uint32_t dst = base + (uint32_t)((p ? SA_AL : 0) + row*40 + c16) * 2;
            CP16(dst, src, nb*2);
        }
        for (int b2 = tid; b2 < BN*8; b2 += 256) {
            int p = b2 / (BN*4), rem = b2 % (BN*4);
            int row = rem >> 2, c16 = (rem & 3) * 8;
            int gr = col0 + row, gk = k0 + c16;
            int nb = 0;
            if (gr < N && gk < K) { nb = K - gk; if (nb > 8) nb = 8; }
            if (gr >= N) gr = col0;
            if (gk >= K) gk = 0;
            const __nv_bfloat16* src = (p ? B_l : B_h) + (ll)gr * ldb + gk;
            uint32_t dst = base + (uint32_t)((p ? SB_L : SB_H) + row*40 + c16) * 2;
            CP16(dst, src, nb*2);
        }
    };

    int w = tid >> 5, l = tid & 31;
    int wm = w % WM, wn = w / WM;
    int a_row = l & 15, a_kc = (l >> 4) * 8;
    int b_row = l & 7,  b_kc = ((l >> 3) & 1) * 8;

    auto comp = [&](int slot) {
        uint32_t base = sb0 + (uint32_t)slot * STG * 2;
#pragma unroll
        for (int kh = 0; kh < 32; kh += 16) {
            uint32_t Ahf[MG][4], Alf[MG][4], Bhf[4][2], Blf[4][2];
#pragma unroll
            for (int mg = 0; mg < MG; mg++) {
                int mrow = wm*WTM + mg*16 + a_row;
                uint32_t ad = base + (uint32_t)(mrow*40 + kh + a_kc) * 2;
                ldm_x4(Ahf[mg], ad);
                ldm_x4(Alf[mg], ad + SA_AL*2);
            }
#pragma unroll
            for (int ng = 0; ng < 4; ng++) {
                int nrow = wn*32 + ng*8 + b_row;
                uint32_t bd = base + (uint32_t)(SB_H + nrow*40 + kh + b_kc) * 2;
                ldm_x2(Bhf[ng], bd);
                ldm_x2(Blf[ng], bd + (SB_L - SB_H)*2);
            }
#pragma unroll
            for (int mg = 0; mg < MG; mg++)
#pragma unroll
                for (int ng = 0; ng < 4; ng++) {
                    mma_bf16(acc[mg][ng], Ahf[mg], Bhf[ng]);
                    mma_bf16(acc[mg][ng], Ahf[mg], Blf[ng]);
                    mma_bf16(acc[mg][ng], Alf[mg], Bhf[ng]);
                }
        }
    };

    int nk = (K + 31) / 32;
    for (int s = 0; s < PIPE-1; s++) {
        if (s < nk) load_stage(s, s*32);
        CP_COMMIT();
    }
    for (int i = 0; i < nk; i++) {
        CP_WAIT(PIPE-2);
        __syncthreads();
        int pf = i + PIPE - 1;
        if (pf < nk) load_stage(pf % PIPE, pf*32);
        CP_COMMIT();
        comp(i % PIPE);
    }

    // ---- epilogue ----
    const float* Rp = R ? (R + (ll)bz * sR) : (const float*)0;
    float* Cp = Cc ? (Cc + (ll)bz * sC) : (float*)0;
    __nv_bfloat16* Op = Ob ? (Ob + (ll)bz * sC) : (__nv_bfloat16*)0;
    int mbase = row0 + wm*WTM;
    int nbase = col0 + wn*32;
#pragma unroll
    for (int mg = 0; mg < MG; mg++) {
#pragma unroll
        for (int ng = 0; ng < 4; ng++) {
            int cc = nbase + ng*8 + (l & 3)*2;
#pragma unroll
            for (int h2 = 0; h2 < 2; h2++) {
                int r = mbase + mg*16 + (l >> 2) + h2*8;
                if (r < M && cc < N) {
                    float o0 = acc[mg][ng][h2*2+0];
                    float o1 = acc[mg][ng][h2*2+1];
                    if (bias) { o0 += bias[cc]; o1 += bias[cc+1]; }
                    if (act == ACT_SILU) {
                        o0 *= 1.f/(1.f+__expf(-o0));
                        o1 *= 1.f/(1.f+__expf(-o1));
                    } else if (act == ACT_SIG) {
                        o0 = 1.f/(1.f+__expf(-o0));
                        o1 = 1.f/(1.f+__expf(-o1));
                    }
                    if (Rp) {
                        float2 rr = *(const float2*)(Rp + (ll)r * ldr + cc);
                        o0 += rr.x; o1 += rr.y;
                    }
                    if (Cp) {
                        float2 ov; ov.x = o0; ov.y = o1;
                        *(float2*)(Cp + (ll)r * ldc + cc) = ov;
                    }
                    if (Op) {
                        __nv_bfloat16 h0 = __float2bfloat16(o0);
                        __nv_bfloat16 h1 = __float2bfloat16(o1);
                        __nv_bfloat162 hv; hv.x = h0; hv.y = h1;
                        __nv_bfloat162 lv;
                        lv.x = __float2bfloat16(o0 - __bfloat162float(h0));
                        lv.y = __float2bfloat16(o1 - __bfloat162float(h1));
                        *(__nv_bfloat162*)(Op + (ll)r * ldc + cc) = hv;
                        *(__nv_bfloat162*)(Op + oE + (ll)r * ldc + cc) = lv;
                    }
                }
            }
        }
    }
}

#define SMEM128 ((2*128 + 2*128)*40*2*3)
#define SMEM64  ((2*128 + 2*64)*40*2*3)

// ---------------- split / transpose kernels ----------------
__global__ void split_nt_k(const float* __restrict__ in, __nv_bfloat16* __restrict__ ob,
                           ll oE, ll n)
{
    ll i = (ll)blockIdx.x * blockDim.x + threadIdx.x;
    if (i >= n) return;
    split_store(ob, oE, i, in[i]);
}

__global__ void split_tr_k(const float* __restrict__ in, __nv_bfloat16* __restrict__ ob,
                           ll oE, int R, int Cn, ll sIn, ll sOut)
{
    __shared__ float t[32][33];
    in += (ll)blockIdx.z * sIn;
    ll obase = (ll)blockIdx.z * sOut;
    int c0 = blockIdx.x * 32, r0 = blockIdx.y * 32;
    int x = threadIdx.x, y = threadIdx.y;   // (32,8)
#pragma unroll
    for (int j = 0; j < 4; j++) {
        int r = r0 + y + 8*j;
        if (r < R && c0 + x < Cn) t[y + 8*j][x] = in[(ll)r * Cn + c0 + x];
    }
    __syncthreads();
#pragma unroll
    for (int j = 0; j < 4; j++) {
        int c = c0 + y + 8*j;
        int r = r0 + x;
        if (c < Cn && r < R) split_store(ob, oE, obase + (ll)c * R + r, t[x][y + 8*j]);
    }
}

// ---------------- fused elementwise kernels ----------------
__global__ void seg_split_k(const float* __restrict__ x, int ch,
                            float* __restrict__ segf, __nv_bfloat16* __restrict__ ob, ll oE)
{
    ll i = (ll)blockIdx.x * blockDim.x + threadIdx.x;
    if (i >= L_MCD) return;
    int d = (int)(i % Dq);
    ll row = i / Dq;
    int b = (int)(row / Cq), t = (int)(row % Cq);
    float v = x[((ll)b*Tq + (ll)ch*Cq + t) * Dq + d];
    segf[i] = v;
    split_store(ob, oE, i, v);
}

__global__ void aug_k(float* __restrict__ aug, const float* __restrict__ pers,
                      const float* __restrict__ h, const float* __restrict__ seg)
{
    ll i = (ll)blockIdx.x * blockDim.x + threadIdx.x;
    if (i >= L_MSD) return;
    int d = (int)(i % Dq);
    ll row = i / Dq;
    int b = (int)(row / Sq), s = (int)(row % Sq);
    float v;
    if (s < Pq)            v = pers[(ll)s*Dq + d];
    else if (s < Pq+Cq)    v = h[((ll)b*Cq + (s-Pq)) * Dq + d];
    else                   v = seg[((ll)b*Cq + (s-Pq-Cq)) * Dq + d];
    aug[i] = v;
}

__global__ void ln_split_k(const float* __restrict__ src, __nv_bfloat16* __restrict__ ob,
                           ll oE, const float* __restrict__ g, const float* __restrict__ b)
{
    ll row = blockIdx.x;
    const float* p = src + row * Dq;
    __shared__ float red[256];
    int t = threadIdx.x;
    float s = 0.f;
    for (int j = t; j < Dq; j += 256) s += p[j];
    red[t] = s; __syncthreads();
    for (int k = 128; k > 0; k >>= 1) { if (t < k) red[t] += red[t+k]; __syncthreads(); }
    float mean = red[0] / (float)Dq;
    __syncthreads();
    float vs = 0.f;
    for (int j = t; j < Dq; j += 256) { float d = p[j] - mean; vs += d*d; }
    red[t] = vs; __syncthreads();
    for (int k = 128; k > 0; k >>= 1) { if (t < k) red[t] += red[t+k]; __syncthreads(); }
    float inv = rsqrtf(red[0] / (float)Dq + 1e-5f);
    for (int j = t; j < Dq; j += 256)
        split_store(ob, oE, row*Dq + j, (p[j] - mean) * inv * g[j] + b[j]);
}

__global__ void l2norm_split_k(const float* __restrict__ src, __nv_bfloat16* __restrict__ ob,
                               ll oE, float scale)
{
    ll row = blockIdx.x;
    const float* p = src + row * Dq;
    __shared__ float red[256];
    int t = threadIdx.x;
    float s = 0.f;
    for (int j = t; j < Dq; j += 256) { float v = p[j]; s += v*v; }
    red[t] = s; __syncthreads();
    for (int k = 128; k > 0; k >>= 1) { if (t < k) red[t] += red[t+k]; __syncthreads(); }
    float inv = scale / fmaxf(sqrtf(red[0]), 1e-12f);
    for (int j = t; j < Dq; j += 256)
        split_store(ob, oE, row*Dq + j, p[j] * inv);
}

__global__ void softmax_split_k(float* __restrict__ sc, __nv_bfloat16* __restrict__ ob, ll oE)
{
    ll row = blockIdx.x;               // 0..MC-1
    int qi = (int)(row % Cq);
    float* p = sc + row * Sq;
    int L = Pq + Cq + qi + 1;
    __shared__ float red[256];
    int t = threadIdx.x;
    float mx = -1e30f;
    for (int j = t; j < L; j += 256) mx = fmaxf(mx, p[j]);
    red[t] = mx; __syncthreads();
    for (int k = 128; k > 0; k >>= 1) { if (t < k) red[t] = fmaxf(red[t], red[t+k]); __syncthreads(); }
    mx = red[0]; __syncthreads();
    float sum = 0.f;
    for (int j = t; j < L; j += 256) { float e = __expf(p[j] - mx); p[j] = e; sum += e; }
    red[t] = sum; __syncthreads();
    for (int k = 128; k > 0; k >>= 1) { if (t < k) red[t] += red[t+k]; __syncthreads(); }
    float inv = 1.f / red[0];
    for (int j = t; j < L; j += 256)
        split_store(ob, oE, row*Sq + j, p[j] * inv);
    for (int j = L + t; j < Sq; j += 256) {
        ob[row*Sq + j] = __float2bfloat16(0.f);
        ob[oE + row*Sq + j] = __float2bfloat16(0.f);
    }
}

__global__ void silu_split_k(const float* __restrict__ pre, float* __restrict__ hf,
                             __nv_bfloat16* __restrict__ ob, ll oE, ll n)
{
    ll i = (ll)blockIdx.x * blockDim.x + threadIdx.x;
    if (i >= n) return;
    float z = pre[i];
    float v = z / (1.f + __expf(-z));
    hf[i] = v;
    split_store(ob, oE, i, v);
}

__global__ void e_split_k(const float* __restrict__ ym, const float* __restrict__ vv,
                          float* __restrict__ ef, __nv_bfloat16* __restrict__ ob, ll oE, ll n)
{
    ll i = (ll)blockIdx.x * blockDim.x + threadIdx.x;
    if (i >= n) return;
    float v = (ym[i] - vv[i]) * (1.f / (float)MC);
    ef[i] = v;
    split_store(ob, oE, i, v);
}

__global__ void dsilu_k(float* __restrict__ dh, const float* __restrict__ pre, ll n)
{
    ll i = (ll)blockIdx.x * blockDim.x + threadIdx.x;
    if (i >= n) return;
    float z = pre[i];
    float s = 1.f / (1.f + __expf(-z));
    dh[i] *= s * (1.f + z * (1.f - s));
}

__global__ void comb_ln_split_k(const float* __restrict__ yt, const float* __restrict__ gate,
                                const float* __restrict__ mo,
                                const float* __restrict__ g, const float* __restrict__ b,
                                float* __restrict__ obf, __nv_bfloat16* __restrict__ onb, ll oE)
{
    ll row = blockIdx.x;
    int t = threadIdx.x;
    const float* yp = yt + row*Dq;
    const float* gp = gate + row*Dq;
    const float* mp = mo + row*Dq;
    float v[4];
    float s = 0.f;
#pragma unroll
    for (int j0 = 0; j0 < 4; j0++) {
        int j = j0*256 + t;
        float ga = gp[j];
        v[j0] = yp[j]*ga + mp[j]*(1.f - ga);
        obf[row*Dq + j] = v[j0];
        s += v[j0];
    }
    __shared__ float red[256];
    red[t] = s; __syncthreads();
    for (int k = 128; k > 0; k >>= 1) { if (t < k) red[t] += red[t+k]; __syncthreads(); }
    float mean = red[0] / (float)Dq;
    __syncthreads();
    float vs = 0.f;
#pragma unroll
    for (int j0 = 0; j0 < 4; j0++) { float d = v[j0] - mean; vs += d*d; }
    red[t] = vs; __syncthreads();
    for (int k = 128; k > 0; k >>= 1) { if (t < k) red[t] += red[t+k]; __syncthreads(); }
    float inv = rsqrtf(red[0] / (float)Dq + 1e-5f);
#pragma unroll
    for (int j0 = 0; j0 < 4; j0++) {
        int j = j0*256 + t;
        split_store(onb, oE, row*Dq + j, (v[j0] - mean) * inv * g[j] + b[j]);
    }
}

// deterministic split-row column sum
__global__ void colsum1_k(float* __restrict__ part, const float* __restrict__ src, int Mr, int N)
{
    int c = blockIdx.x * blockDim.x + threadIdx.x;
    if (c >= N) return;
    int r0 = blockIdx.y * 64;
    int r1 = min(r0 + 64, Mr);
    float s = 0.f;
    for (int r = r0; r < r1; r++) s += src[(ll)r * N + c];
    part[(ll)blockIdx.y * N + c] = s;
}
__global__ void colsum2_k(float* __restrict__ dst, const float* __restrict__ part, int ny, int N)
{
    int c = blockIdx.x * blockDim.x + threadIdx.x;
    if (c >= N) return;
    float s = 0.f;
    for (int r = 0; r < ny; r++) s += part[(ll)r * N + c];
    dst[c] = s;
}

__global__ void update_k(float* __restrict__ p, float* __restrict__ m,
                         const float* __restrict__ g, ll n)
{
    ll i = (ll)blockIdx.x * blockDim.x + threadIdx.x;
    if (i >= n) return;
    float mm = 0.9f * m[i] + g[i];
    m[i] = mm;
    p[i] = 0.99f * p[i] - 0.01f * mm;
}

// ---------------- host helpers ----------------
static inline int blks(ll n) { return (int)((n + 255) / 256); }

typedef __nv_bfloat16 bf;

static void g3(const bf* A, ll aE, const bf* B, ll bE,
               const float* bias, const float* R, float* C, bf* Ob, ll oE,
               int M, int N, int K, int lda, int ldb, int ldc, int ldr,
               ll sA, ll sB, ll sR, ll sC, int batch, int act)
{
    ll ct = (ll)((M + 127)/128) * ((N + 127)/128) * batch;
    if (ct >= 120) {
        dim3 g((N + 127)/128, (M + 127)/128, batch);
        g3_k<128><<<g, 256, SMEM128>>>(A, aE, B, bE, bias, R, C, Ob, oE,
                                       M, N, K, lda, ldb, ldc, ldr, sA, sB, sR, sC, act);
    } else {
        dim3 g((N + 63)/64, (M + 127)/128, batch);
        g3_k<64><<<g, 256, SMEM64>>>(A, aE, B, bE, bias, R, C, Ob, oE,
                                     M, N, K, lda, ldb, ldc, ldr, sA, sB, sR, sC, act);
    }
}

static void split_tr(const float* in, bf* ob, ll oE, int R, int Cn,
                     ll sIn = 0, ll sOut = 0, int batch = 1)
{
    dim3 g((Cn + 31)/32, (R + 31)/32, batch);
    split_tr_k<<<g, dim3(32, 8)>>>(in, ob, oE, R, Cn, sIn, sOut);
}

static void colsum(float* dst, float* part, const float* src, int Mr, int N)
{
    int ny = (Mr + 63) / 64;
    dim3 g1((N + 255)/256, ny);
    colsum1_k<<<g1, 256>>>(part, src, Mr, N);
    colsum2_k<<<(N + 255)/256, 256>>>(dst, part, ny, N);
}

extern "C" void kernel_launch(void* const* d_in, const int* in_sizes, int n_in,
                              void* d_out, int out_size)
{
    (void)in_sizes; (void)n_in; (void)out_size;
    const float* x         = (const float*)d_in[0];
    const float* wq_ctx    = (const float*)d_in[1];
    const float* wq        = (const float*)d_in[2];
    const float* wk        = (const float*)d_in[3];
    const float* wv        = (const float*)d_in[4];
    const float* w_attn_out= (const float*)d_in[5];
    const float* w_gate    = (const float*)d_in[6];
    const float* gate_g    = (const float*)d_in[7];
    const float* gate_b    = (const float*)d_in[8];
    const float* n1_g      = (const float*)d_in[9];
    const float* n1_b      = (const float*)d_in[10];
    const float* n2_g      = (const float*)d_in[11];
    const float* n2_b      = (const float*)d_in[12];
    const float* ffn_w1    = (const float*)d_in[13];
    const float* ffn_b1    = (const float*)d_in[14];
    const float* ffn_w2    = (const float*)d_in[15];
    const float* ffn_b2    = (const float*)d_in[16];
    const float* pers      = (const float*)d_in[17];
    const float* mem_w0    = (const float*)d_in[18];
    const float* mem_b0    = (const float*)d_in[19];
    const float* mem_w1    = (const float*)d_in[20];
    const float* mem_b1    = (const float*)d_in[21];
    const float* mem_wk    = (const float*)d_in[22];
    const float* mem_wv    = (const float*)d_in[23];
    float* out = (float*)d_out;

    cudaFuncSetAttribute(g3_k<128>, cudaFuncAttributeMaxDynamicSharedMemorySize, SMEM128);
    cudaFuncSetAttribute(g3_k<64>,  cudaFuncAttributeMaxDynamicSharedMemorySize, SMEM64);

    float* fb; cudaGetSymbolAddress((void**)&fb, g_f);
    bf* bb;    cudaGetSymbolAddress((void**)&bb, g_b);

    float* seg  = fb + F_SEG;   float* qn   = fb + F_QN;
    float* pre  = fb + F_PRE;   float* hsil = fb + F_HSIL;
    float* hbuf = fb + F_H;     float* aug  = fb + F_AUG;
    float* kbf  = fb + F_KB;    float* vbf  = fb + F_VB;
    float* qbf  = fb + F_QB;    float* scr  = fb + F_SCR;
    float* yt   = fb + F_YT;    float* kk   = fb + F_KK;
    float* vv   = fb + F_VV;    float* ym   = fb + F_YM;
    float* eb   = fb + F_EB;    float* dh   = fb + F_DH;
    float* gw0  = fb + F_GW0;   float* gw1  = fb + F_GW1;
    float* gb0  = fb + F_GB0;   float* gb1  = fb + F_GB1;
    float* W0p  = fb + F_W0;    float* B0p  = fb + F_B0;
    float* W1p  = fb + F_W1;    float* B1p  = fb + F_B1;
    float* M0p  = fb + F_M0;    float* MB0p = fb + F_MB0;
    float* M1p  = fb + F_M1;    float* MB1p = fb + F_MB1;
    float* mo   = fb + F_MO;    float* gate = fb + F_GATE;
    float* ob   = fb + F_OB;    float* CS   = fb + F_CS;

    bf* SegB = bb + BO_SEG;   bf* QnB  = bb + BO_QN;
    bf* HsB  = bb + BO_HSIL;  bf* LnagB= bb + BO_LNAG;
    bf* KbB  = bb + BO_KB;    bf* QbB  = bb + BO_QB;
    bf* VbTB = bb + BO_VBT;   bf* ScrB = bb + BO_SCR;
    bf* AttB = bb + BO_ATT;   bf* YtB  = bb + BO_YT;
    bf* KkB  = bb + BO_KK;    bf* KkTB = bb + BO_KKT;
    bf* EbB  = bb + BO_EB;    bf* EbTB = bb + BO_EBT;
    bf* HsTB = bb + BO_HST;   bf* DhTB = bb + BO_DHT;
    bf* LnyB = bb + BO_LNY;   bf* FfhB = bb + BO_FFH;
    bf* W0TB = bb + BO_W0T;   bf* W1TB = bb + BO_W1T;
    bf* W1NB = bb + BO_W1N;
    bf* TQCb = bb + BO_TQC;   bf* TQb  = bb + BO_TQ;
    bf* TKb  = bb + BO_TK;    bf* TVb  = bb + BO_TV;
    bf* TAOb = bb + BO_TAO;   bf* TGb  = bb + BO_TG;
    bf* TMKb = bb + BO_TMK;   bf* TMVb = bb + BO_TMV;
    bf* TF1b = bb + BO_TF1;   bf* TF2b = bb + BO_TF2;

    // init memory state + zero momentum (every call: deterministic)
    cudaMemcpyAsync(W0p, mem_w0, L_W0 * sizeof(float), cudaMemcpyDeviceToDevice);
    cudaMemcpyAsync(B0p, mem_b0, Hq   * sizeof(float), cudaMemcpyDeviceToDevice);
    cudaMemcpyAsync(W1p, mem_w1, L_W0 * sizeof(float), cudaMemcpyDeviceToDevice);
    cudaMemcpyAsync(B1p, mem_b1, Dq   * sizeof(float), cudaMemcpyDeviceToDevice);
    cudaMemsetAsync(M0p,  0, L_W0 * sizeof(float));
    cudaMemsetAsync(MB0p, 0, Hq   * sizeof(float));
    cudaMemsetAsync(M1p,  0, L_W0 * sizeof(float));
    cudaMemsetAsync(MB1p, 0, Dq   * sizeof(float));

    // static weight splits (K-major B operands: (N,K) = W^T)
    split_tr(wq_ctx,     TQCb, L_DD, Dq, Dq);
    split_tr(wq,         TQb,  L_DD, Dq, Dq);
    split_tr(wk,         TKb,  L_DD, Dq, Dq);
    split_tr(wv,         TVb,  L_DD, Dq, Dq);
    split_tr(w_attn_out, TAOb, L_DD, Dq, Dq);
    split_tr(w_gate,     TGb,  L_DD, Dq, Dq);
    split_tr(mem_wk,     TMKb, L_DD, Dq, Dq);
    split_tr(mem_wv,     TMVb, L_DD, Dq, Dq);
    split_tr(ffn_w1,     TF1b, (ll)Dq*FFNq, Dq, FFNq);
    split_tr(ffn_w2,     TF2b, (ll)FFNq*Dq, FFNq, Dq);
    // memory weight splits (redone after each update)
    split_tr(W0p, W0TB, L_W0, Dq, Hq);
    split_tr(W1p, W1TB, L_W0, Hq, Dq);
    split_nt_k<<<blks(L_W0), 256>>>(W1p, W1NB, L_W0, L_W0);

    for (int ch = 0; ch < NCHUNK; ch++) {
        seg_split_k<<<blks(L_MCD), 256>>>(x, ch, seg, SegB, L_MCD);

        // h = mem_mlp(mem, l2norm(seg @ wq_ctx))
        g3(SegB, L_MCD, TQCb, L_DD, 0, 0, qn, 0, 0,
           MC, Dq, Dq, Dq, Dq, Dq, 0, 0,0,0,0, 1, ACT_NONE);
        l2norm_split_k<<<MC, 256>>>(qn, QnB, L_MCD, 1.0f);
        g3(QnB, L_MCD, W0TB, L_W0, B0p, 0, 0, HsB, L_MCH,
           MC, Hq, Dq, Dq, Dq, Hq, 0, 0,0,0,0, 1, ACT_SILU);
        g3(HsB, L_MCH, W1TB, L_W0, B1p, 0, hbuf, 0, 0,
           MC, Dq, Hq, Hq, Hq, Dq, 0, 0,0,0,0, 1, ACT_NONE);

        aug_k<<<blks(L_MSD), 256>>>(aug, pers, hbuf, seg);
        ln_split_k<<<MS, 256>>>(aug, LnagB, L_MSD, n1_g, n1_b);

        g3(LnagB, L_MSD, TKb, L_DD, 0, 0, kbf, 0, 0,
           MS, Dq, Dq, Dq, Dq, Dq, 0, 0,0,0,0, 1, ACT_NONE);
        l2norm_split_k<<<MS, 256>>>(kbf, KbB, L_MSD, 1.0f);
        g3(LnagB, L_MSD, TVb, L_DD, 0, 0, vbf, 0, 0,
           MS, Dq, Dq, Dq, Dq, Dq, 0, 0,0,0,0, 1, ACT_NONE);
        split_tr(vbf, VbTB, L_MSD, Sq, Dq, (ll)Sq*Dq, (ll)Dq*Sq, Bq);
        g3(LnagB + (ll)(Pq+Cq)*Dq, L_MSD, TQb, L_DD, 0, 0, qbf, 0, 0,
           Cq, Dq, Dq, Dq, Dq, Dq, 0, (ll)Sq*Dq, 0, 0, (ll)Cq*Dq, Bq, ACT_NONE);
        l2norm_split_k<<<MC, 256>>>(qbf, QbB, L_MCD, 32.0f);   // * sqrt(D)

        // scores = q @ k^T ; causal softmax ; @ v ; @ w_attn_out + seg
        g3(QbB, L_MCD, KbB, L_MSD, 0, 0, scr, 0, 0,
           Cq, Sq, Dq, Dq, Dq, Sq, 0, (ll)Cq*Dq, (ll)Sq*Dq, 0, (ll)Cq*Sq, Bq, ACT_NONE);
        softmax_split_k<<<MC, 256>>>(scr, ScrB, (ll)MC*Sq);
        g3(ScrB, (ll)MC*Sq, VbTB, L_MSD, 0, 0, 0, AttB, L_MCD,
           Cq, Dq, Sq, Sq, Sq, Dq, 0, (ll)Cq*Sq, (ll)Dq*Sq, 0, (ll)Cq*Dq, Bq, ACT_NONE);
        g3(AttB, L_MCD, TAOb, L_DD, 0, seg, yt, YtB, L_MCD,
           MC, Dq, Dq, Dq, Dq, Dq, Dq, 0,0,0,0, 1, ACT_NONE);

        // memory inner update
        g3(YtB, L_MCD, TMKb, L_DD, 0, 0, kk, KkB, L_MCD,
           MC, Dq, Dq, Dq, Dq, Dq, 0, 0,0,0,0, 1, ACT_NONE);
        g3(YtB, L_MCD, TMVb, L_DD, 0, 0, vv, 0, 0,
           MC, Dq, Dq, Dq, Dq, Dq, 0, 0,0,0,0, 1, ACT_NONE);
        g3(KkB, L_MCD, W0TB, L_W0, B0p, 0, pre, 0, 0,
           MC, Hq, Dq, Dq, Dq, Hq, 0, 0,0,0,0, 1, ACT_NONE);
        silu_split_k<<<blks(L_MCH), 256>>>(pre, hsil, HsB, L_MCH, L_MCH);
        g3(HsB, L_MCH, W1TB, L_W0, B1p, 0, ym, 0, 0,
           MC, Dq, Hq, Hq, Hq, Dq, 0, 0,0,0,0, 1, ACT_NONE);
        e_split_k<<<blks(L_MCD), 256>>>(ym, vv, eb, EbB, L_MCD, L_MCD);
        split_tr(hsil, HsTB, L_MCH, MC, Hq);
        split_tr(eb,   EbTB, L_MCD, MC, Dq);
        g3(HsTB, L_MCH, EbTB, L_MCD, 0, 0, gw1, 0, 0,
           Hq, Dq, MC, MC, MC, Dq, 0, 0,0,0,0, 1, ACT_NONE);
        colsum(gb1, CS, eb, MC, Dq);
        g3(EbB, L_MCD, W1NB, L_W0, 0, 0, dh, 0, 0,
           MC, Hq, Dq, Dq, Dq, Hq, 0, 0,0,0,0, 1, ACT_NONE);
        dsilu_k<<<blks(L_MCH), 256>>>(dh, pre, L_MCH);
        split_tr(kk, KkTB, L_MCD, MC, Dq);
        split_tr(dh, DhTB, L_MCH, MC, Hq);
        g3(KkTB, L_MCD, DhTB, L_MCH, 0, 0, gw0, 0, 0,
           Dq, Hq, MC, MC, MC, Hq, 0, 0,0,0,0, 1, ACT_NONE);
        colsum(gb0, CS, dh, MC, Hq);
        update_k<<<blks(L_W0), 256>>>(W0p, M0p, gw0, L_W0);
        update_k<<<blks(Hq), 256>>>(B0p, MB0p, gb0, Hq);
        update_k<<<blks(L_W0), 256>>>(W1p, M1p, gw1, L_W0);
        update_k<<<blks(Dq), 256>>>(B1p, MB1p, gb1, Dq);
        split_tr(W0p, W0TB, L_W0, Dq, Hq);
        split_tr(W1p, W1TB, L_W0, Hq, Dq);
        split_nt_k<<<blks(L_W0), 256>>>(W1p, W1NB, L_W0, L_W0);

        // mem_out with updated memory
        g3(YtB, L_MCD, TQCb, L_DD, 0, 0, qn, 0, 0,
           MC, Dq, Dq, Dq, Dq, Dq, 0, 0,0,0,0, 1, ACT_NONE);
        l2norm_split_k<<<MC, 256>>>(qn, QnB, L_MCD, 1.0f);
        g3(QnB, L_MCD, W0TB, L_W0, B0p, 0, 0, HsB, L_MCH,
           MC, Hq, Dq, Dq, Dq, Hq, 0, 0,0,0,0, 1, ACT_SILU);
        g3(HsB, L_MCH, W1TB, L_W0, B1p, 0, mo, 0, 0,
           MC, Dq, Hq, Hq, Hq, Dq, 0, 0,0,0,0, 1, ACT_NONE);

        // gate + combine + LN2 (fused)
        ln_split_k<<<MC, 256>>>(yt, LnyB, L_MCD, gate_g, gate_b);
        g3(LnyB, L_MCD, TGb, L_DD, 0, 0, gate, 0, 0,
           MC, Dq, Dq, Dq, Dq, Dq, 0, 0,0,0,0, 1, ACT_SIG);
        comb_ln_split_k<<<MC, 256>>>(yt, gate, mo, n2_g, n2_b, ob, LnyB, L_MCD);

        // FFN with residual -> output slice
        g3(LnyB, L_MCD, TF1b, (ll)Dq*FFNq, ffn_b1, 0, 0, FfhB, (ll)MC*FFNq,
           MC, FFNq, Dq, Dq, Dq, FFNq, 0, 0,0,0,0, 1, ACT_SILU);
        g3(FfhB, (ll)MC*FFNq, TF2b, (ll)FFNq*Dq, ffn_b2, ob, out + (ll)ch*Cq*Dq, 0, 0,
           Cq, Dq, FFNq, FFNq, FFNq, Dq, Dq,
           (ll)Cq*FFNq, 0, (ll)Cq*Dq, (ll)Tq*Dq, Bq, ACT_NONE);
    }
}